// round 1
// baseline (speedup 1.0000x reference)
#include <cuda_runtime.h>

#define DM   1024
#define NH   16
#define DK   64
#define BATCH 2
#define SEQ  2048
#define MROWS (BATCH*SEQ)   // 4096
#define GP   68             // smem row pitch (floats): 16B-aligned rows, low-conflict

// Scratch (sanctioned __device__ globals; no allocation in kernel_launch)
__device__ float g_Q[BATCH*NH*SEQ*DK];
__device__ float g_K[BATCH*NH*SEQ*DK];
__device__ float g_V[BATCH*NH*SEQ*DK];
__device__ float g_ctx[MROWS*DM];

// ---------------------------------------------------------------------------
// GEMM: C[m][n] = sum_k A[m][k] * W[n][k] + bias[n]
// A row-major [M, DM], W row-major [DM_out=1024, DM], 64x64 tile, 256 threads,
// 4x4 register micro-tile, both operands stored k-transposed in smem so the
// inner loop is two float4 LDS + 16 FFMA.
// head_layout=1: write C to head-split [b, h, s, d] scratch (n tile == head).
// ---------------------------------------------------------------------------
__global__ __launch_bounds__(256)
void gemm_proj(const float* __restrict__ A, const float* __restrict__ W,
               const float* __restrict__ bias, float* __restrict__ C,
               int head_layout)
{
    __shared__ __align__(16) float As[64*GP]; // As[k*GP + m]
    __shared__ __align__(16) float Bs[64*GP]; // Bs[k*GP + n]

    const int m0 = blockIdx.y * 64;
    const int n0 = blockIdx.x * 64;
    const int tid = threadIdx.x;
    const int tx = tid & 15;   // n direction (4 cols each)
    const int ty = tid >> 4;   // m direction (4 rows each)

    float acc[4][4];
#pragma unroll
    for (int i = 0; i < 4; i++)
#pragma unroll
        for (int j = 0; j < 4; j++) acc[i][j] = 0.f;

    for (int kt = 0; kt < DM; kt += 64) {
#pragma unroll
        for (int i = 0; i < 16; i++) {
            int idx = tid + i * 256;
            int r = idx >> 6, k = idx & 63;
            As[k*GP + r] = A[(size_t)(m0 + r) * DM + kt + k];
            Bs[k*GP + r] = W[(size_t)(n0 + r) * DM + kt + k];
        }
        __syncthreads();
#pragma unroll 8
        for (int k = 0; k < 64; k++) {
            float4 av = *(const float4*)&As[k*GP + ty*4];
            float4 bv = *(const float4*)&Bs[k*GP + tx*4];
            float a[4] = {av.x, av.y, av.z, av.w};
            float b[4] = {bv.x, bv.y, bv.z, bv.w};
#pragma unroll
            for (int i = 0; i < 4; i++)
#pragma unroll
                for (int j = 0; j < 4; j++)
                    acc[i][j] = fmaf(a[i], b[j], acc[i][j]);
        }
        __syncthreads();
    }

    // epilogue: bias + store
#pragma unroll
    for (int i = 0; i < 4; i++) {
        int m = m0 + ty*4 + i;
        float4 v;
        v.x = acc[i][0] + bias[n0 + tx*4 + 0];
        v.y = acc[i][1] + bias[n0 + tx*4 + 1];
        v.z = acc[i][2] + bias[n0 + tx*4 + 2];
        v.w = acc[i][3] + bias[n0 + tx*4 + 3];
        if (head_layout) {
            int h = n0 >> 6;          // BN==DK==64 -> one head per n-tile
            int b = m >> 11;          // /SEQ
            int s = m & (SEQ - 1);
            *(float4*)&C[(((size_t)(b*NH + h) * SEQ + s) * DK) + tx*4] = v;
        } else {
            *(float4*)&C[(size_t)m * DM + n0 + tx*4] = v;
        }
    }
}

// ---------------------------------------------------------------------------
// Flash attention, fp32. One block = 64 query rows of one (b,h).
// Online softmax; K-tile and V-tile share one smem buffer (phase-separated).
// Scale 1/sqrt(dk) folded into the Q tile load.
// ctx written in [b, s, h, d] layout == concat layout for the out projection.
// ---------------------------------------------------------------------------
extern __shared__ float attn_smem[];

__global__ __launch_bounds__(256)
void attn_kernel(const float* __restrict__ Q, const float* __restrict__ K,
                 const float* __restrict__ V, float* __restrict__ ctx)
{
    float* Qs = attn_smem;            // [d][r]  Qs[d*GP + r]   (pre-scaled)
    float* KV = attn_smem + 64*GP;    // K phase: [d][c]; V phase: [s][d]
    float* Ps = attn_smem + 2*64*GP;  // [s][r]  P transposed

    const int bh = blockIdx.y;
    const int q0 = blockIdx.x * 64;
    const size_t base = (size_t)bh * SEQ * DK;
    const int tid = threadIdx.x;
    const int tx = tid & 15;
    const int ty = tid >> 4;

    // Load Q tile transposed, folding in softmax scale (1/8)
#pragma unroll
    for (int i = 0; i < 16; i++) {
        int idx = tid + i * 256;
        int r = idx >> 6, d = idx & 63;
        Qs[d*GP + r] = 0.125f * Q[base + (size_t)(q0 + r) * DK + d];
    }

    float mrow[4], lrow[4], accO[4][4];
#pragma unroll
    for (int i = 0; i < 4; i++) {
        mrow[i] = -1e30f; lrow[i] = 0.f;
#pragma unroll
        for (int j = 0; j < 4; j++) accO[i][j] = 0.f;
    }

    for (int s0 = 0; s0 < SEQ; s0 += 64) {
        __syncthreads();  // prev GEMM2 done with KV/Ps; also fences Q load (iter 0)

        // K tile transposed: KV[d][c]
#pragma unroll
        for (int i = 0; i < 16; i++) {
            int idx = tid + i * 256;
            int c = idx >> 6, d = idx & 63;
            KV[d*GP + c] = K[base + (size_t)(s0 + c) * DK + d];
        }
        __syncthreads();

        // S = (Q*scale) . K^T
        float sacc[4][4];
#pragma unroll
        for (int i = 0; i < 4; i++)
#pragma unroll
            for (int j = 0; j < 4; j++) sacc[i][j] = 0.f;
#pragma unroll 8
        for (int k = 0; k < 64; k++) {
            float4 qv = *(const float4*)&Qs[k*GP + ty*4];
            float4 kv = *(const float4*)&KV[k*GP + tx*4];
            float a[4] = {qv.x, qv.y, qv.z, qv.w};
            float b[4] = {kv.x, kv.y, kv.z, kv.w};
#pragma unroll
            for (int i = 0; i < 4; i++)
#pragma unroll
                for (int j = 0; j < 4; j++)
                    sacc[i][j] = fmaf(a[i], b[j], sacc[i][j]);
        }

        // online softmax (row groups = 16 contiguous lanes in a warp)
        float alpha[4];
#pragma unroll
        for (int i = 0; i < 4; i++) {
            float tm = fmaxf(fmaxf(sacc[i][0], sacc[i][1]),
                             fmaxf(sacc[i][2], sacc[i][3]));
#pragma unroll
            for (int mk = 1; mk < 16; mk <<= 1)
                tm = fmaxf(tm, __shfl_xor_sync(0xffffffffu, tm, mk));
            float mn = fmaxf(mrow[i], tm);
            alpha[i] = __expf(mrow[i] - mn);
            mrow[i] = mn;
            float rs = 0.f;
#pragma unroll
            for (int j = 0; j < 4; j++) {
                float p = __expf(sacc[i][j] - mn);
                sacc[i][j] = p;
                rs += p;
            }
#pragma unroll
            for (int mk = 1; mk < 16; mk <<= 1)
                rs += __shfl_xor_sync(0xffffffffu, rs, mk);
            lrow[i] = lrow[i] * alpha[i] + rs;
#pragma unroll
            for (int j = 0; j < 4; j++) accO[i][j] *= alpha[i];
        }

        // store P transposed: Ps[s][r]
#pragma unroll
        for (int j = 0; j < 4; j++) {
            float4 pv = make_float4(sacc[0][j], sacc[1][j], sacc[2][j], sacc[3][j]);
            *(float4*)&Ps[(tx*4 + j)*GP + ty*4] = pv;
        }
        __syncthreads();  // K reads + P writes complete

        // V tile natural layout: KV[s][d]
#pragma unroll
        for (int i = 0; i < 16; i++) {
            int idx = tid + i * 256;
            int r = idx >> 6, d = idx & 63;
            KV[r*GP + d] = V[base + (size_t)(s0 + r) * DK + d];
        }
        __syncthreads();

        // O += P . V
#pragma unroll 8
        for (int s = 0; s < 64; s++) {
            float4 pv = *(const float4*)&Ps[s*GP + ty*4];
            float4 vv = *(const float4*)&KV[s*GP + tx*4];
            float a[4] = {pv.x, pv.y, pv.z, pv.w};
            float b[4] = {vv.x, vv.y, vv.z, vv.w};
#pragma unroll
            for (int i = 0; i < 4; i++)
#pragma unroll
                for (int j = 0; j < 4; j++)
                    accO[i][j] = fmaf(a[i], b[j], accO[i][j]);
        }
    }

    // epilogue: normalize, write ctx in [b, s, h, d] (== concat layout)
    const int b = bh >> 4, h = bh & 15;
#pragma unroll
    for (int i = 0; i < 4; i++) {
        float inv = 1.0f / lrow[i];
        int q = q0 + ty*4 + i;
        float4 v = make_float4(accO[i][0]*inv, accO[i][1]*inv,
                               accO[i][2]*inv, accO[i][3]*inv);
        *(float4*)&ctx[((size_t)(b*SEQ + q) * NH + h) * DK + tx*4] = v;
    }
}

// ---------------------------------------------------------------------------
extern "C" void kernel_launch(void* const* d_in, const int* in_sizes, int n_in,
                              void* d_out, int out_size)
{
    const float* Xq = (const float*)d_in[0];
    const float* Xk = (const float*)d_in[1];
    const float* Xv = (const float*)d_in[2];
    const float* Wq = (const float*)d_in[3];
    const float* bq = (const float*)d_in[4];
    const float* Wk = (const float*)d_in[5];
    const float* bk = (const float*)d_in[6];
    const float* Wv = (const float*)d_in[7];
    const float* bv = (const float*)d_in[8];
    const float* Wo = (const float*)d_in[9];
    const float* bo = (const float*)d_in[10];
    float* out = (float*)d_out;

    float *Qp, *Kp, *Vp, *Cp;
    cudaGetSymbolAddress((void**)&Qp, g_Q);
    cudaGetSymbolAddress((void**)&Kp, g_K);
    cudaGetSymbolAddress((void**)&Vp, g_V);
    cudaGetSymbolAddress((void**)&Cp, g_ctx);

    const int attn_smem_bytes = 3 * 64 * GP * (int)sizeof(float);  // 52224
    cudaFuncSetAttribute(attn_kernel,
                         cudaFuncAttributeMaxDynamicSharedMemorySize,
                         attn_smem_bytes);

    dim3 blk(256);
    dim3 gp(DM/64, MROWS/64);        // 16 x 64
    gemm_proj<<<gp, blk>>>(Xq, Wq, bq, Qp, 1);
    gemm_proj<<<gp, blk>>>(Xk, Wk, bk, Kp, 1);
    gemm_proj<<<gp, blk>>>(Xv, Wv, bv, Vp, 1);

    dim3 ga(SEQ/64, BATCH*NH);       // 32 x 32
    attn_kernel<<<ga, blk, attn_smem_bytes>>>(Qp, Kp, Vp, Cp);

    gemm_proj<<<gp, blk>>>(Cp, Wo, bo, out, 0);
}